// round 14
// baseline (speedup 1.0000x reference)
#include <cuda_runtime.h>

// newIF spiking neuron forward (T=8), memory-bound streaming kernel.
// R14 probe: 256-bit memory ops (sm_10x ld/st.global.v8.f32).
// One thread = 8 neurons; 8 front-batched LDG.E.256 (same instruction-depth
// optimum as R13, double bytes/request). Readout: DRAM% vs 78.7 baseline.

#define T_STEPS 8

struct __align__(32) f8 { float v[8]; };

__device__ __forceinline__ f8 ldg256_cs(const float* p) {
    f8 r;
    asm volatile("ld.global.cs.v8.f32 {%0,%1,%2,%3,%4,%5,%6,%7}, [%8];"
                 : "=f"(r.v[0]), "=f"(r.v[1]), "=f"(r.v[2]), "=f"(r.v[3]),
                   "=f"(r.v[4]), "=f"(r.v[5]), "=f"(r.v[6]), "=f"(r.v[7])
                 : "l"(p));
    return r;
}

__device__ __forceinline__ void stg256_cs(float* p, const f8& r) {
    asm volatile("st.global.cs.v8.f32 [%0], {%1,%2,%3,%4,%5,%6,%7,%8};"
                 :: "l"(p),
                    "f"(r.v[0]), "f"(r.v[1]), "f"(r.v[2]), "f"(r.v[3]),
                    "f"(r.v[4]), "f"(r.v[5]), "f"(r.v[6]), "f"(r.v[7])
                 : "memory");
}

__global__ __launch_bounds__(128) void newif_kernel(
    const float* __restrict__ x,
    const float* __restrict__ thresh,
    float*       __restrict__ out,
    int n8)  // neurons per timestep / 8
{
    int i = blockIdx.x * blockDim.x + threadIdx.x;
    if (i >= n8) return;

    const float thre = __ldg(thresh);
    const float half = 0.5f * thre;
    const float tcap = (float)T_STEPS * thre;

    const long long base = (long long)i * 8;
    const long long row  = (long long)n8 * 8;

    // Front-batched: 8 independent LDG.E.256 (1KB per warp request)
    f8 xv[T_STEPS];
    #pragma unroll
    for (int t = 0; t < T_STEPS; t++)
        xv[t] = ldg256_cs(x + (long long)t * row + base);

    float mem[8], cnt[8];
    unsigned smask[8];
    #pragma unroll
    for (int l = 0; l < 8; l++) { mem[l] = half; cnt[l] = 0.f; smask[l] = 0u; }

    #pragma unroll
    for (int t = 0; t < T_STEPS; t++) {
        #pragma unroll
        for (int l = 0; l < 8; l++) {
            float m = mem[l] + xv[t].v[l];
            if (m >= thre) { m -= thre; cnt[l] += 1.f; smask[l] |= (1u << t); }
            mem[l] = m;
        }
    }

    float nt[8];
    #pragma unroll
    for (int l = 0; l < 8; l++) {
        float compen = mem[l] - half + cnt[l] * thre;
        float cv = fminf(compen, tcap);
        bool cond = (cv > 0.f) && (cnt[l] > 0.f);
        nt[l] = cond ? (cv / cnt[l]) : 0.f;
    }

    #pragma unroll
    for (int t = 0; t < T_STEPS; t++) {
        f8 o;
        #pragma unroll
        for (int l = 0; l < 8; l++)
            o.v[l] = (smask[l] >> t & 1u) ? nt[l] : 0.f;
        stg256_cs(out + (long long)t * row + base, o);
    }
}

extern "C" void kernel_launch(void* const* d_in, const int* in_sizes, int n_in,
                              void* d_out, int out_size) {
    const float* x      = (const float*)d_in[0];
    const float* thresh = (const float*)d_in[1];
    float* out          = (float*)d_out;

    int total = in_sizes[0];          // T * B * C * H * W
    int n_per_t = total / T_STEPS;    // B * C * H * W
    int n8 = n_per_t / 8;             // 8-float units per timestep

    int threads = 128;
    int blocks = (n8 + threads - 1) / threads;
    newif_kernel<<<blocks, threads>>>(x, thresh, out, n8);
}

// round 16
// speedup vs baseline: 1.0151x; 1.0151x over previous
#include <cuda_runtime.h>

// newIF spiking neuron forward (T=8) — FINAL kernel (champion config, R13).
// One thread = 4 neurons (float4), 8 front-batched independent LDG.E.128
// (measured optimum burst depth), 128-thread blocks (measured optimum),
// streaming cache hints.
//
// At the roofline: 512MB mandatory traffic @ 6.23TB/s achieved (78.7% of
// 8TB/s spec) = HBM3e mixed 1:1 R/W ceiling. Closed axes: burst depth
// {4,8,16}, access width {128b,256b}, blocks {64,128,256,512}, occupancy
// 21-81%, all cache-hint combos, grid-stride vs block-parallel.

#define T_STEPS 8

__global__ __launch_bounds__(128) void newif_kernel(
    const float4* __restrict__ x,
    const float*  __restrict__ thresh,
    float4*       __restrict__ out,
    int n4)  // neurons per timestep / 4
{
    int i = blockIdx.x * blockDim.x + threadIdx.x;
    if (i >= n4) return;

    const float thre  = __ldg(thresh);
    const float half  = 0.5f * thre;
    const float tcap  = (float)T_STEPS * thre;

    // Front-batched loads: 8 independent LDG.E.128 (MLP=8 per thread)
    float4 xv[T_STEPS];
    #pragma unroll
    for (int t = 0; t < T_STEPS; t++)
        xv[t] = __ldcs(&x[t * n4 + i]);

    float mem[4] = {half, half, half, half};
    float cnt[4] = {0.f, 0.f, 0.f, 0.f};
    unsigned smask[4] = {0u, 0u, 0u, 0u};

    #pragma unroll
    for (int t = 0; t < T_STEPS; t++) {
        const float* xt = reinterpret_cast<const float*>(&xv[t]);
        #pragma unroll
        for (int l = 0; l < 4; l++) {
            float m = mem[l] + xt[l];
            bool s = (m >= thre);
            if (s) { m -= thre; cnt[l] += 1.f; smask[l] |= (1u << t); }
            mem[l] = m;
        }
    }

    float nt[4];
    #pragma unroll
    for (int l = 0; l < 4; l++) {
        float compen = mem[l] - half + cnt[l] * thre;
        float cv = fminf(compen, tcap);
        bool cond = (cv > 0.f) && (cnt[l] > 0.f);
        nt[l] = cond ? (cv / cnt[l]) : 0.f;
    }

    #pragma unroll
    for (int t = 0; t < T_STEPS; t++) {
        float4 o;
        o.x = (smask[0] >> t & 1u) ? nt[0] : 0.f;
        o.y = (smask[1] >> t & 1u) ? nt[1] : 0.f;
        o.z = (smask[2] >> t & 1u) ? nt[2] : 0.f;
        o.w = (smask[3] >> t & 1u) ? nt[3] : 0.f;
        __stcs(&out[t * n4 + i], o);
    }
}

extern "C" void kernel_launch(void* const* d_in, const int* in_sizes, int n_in,
                              void* d_out, int out_size) {
    const float* x      = (const float*)d_in[0];
    const float* thresh = (const float*)d_in[1];
    float* out          = (float*)d_out;

    int total = in_sizes[0];          // T * B * C * H * W
    int n_per_t = total / T_STEPS;    // B * C * H * W
    int n4 = n_per_t / 4;             // float4 units per timestep

    int threads = 128;
    int blocks = (n4 + threads - 1) / threads;
    newif_kernel<<<blocks, threads>>>(
        (const float4*)x, thresh, (float4*)out, n4);
}